// round 12
// baseline (speedup 1.0000x reference)
#include <cuda_runtime.h>
#include <cuda_fp16.h>
#include <math.h>
#include <stdint.h>

// Problem constants
#define N_NODES 2000
#define F_NODE  128
#define HEADS   8
#define GDIM    64
#define DMODEL  512
#define BATCH   64
#define SEQ     512
#define M_TRIP  (BATCH * SEQ)
#define REGION_ELEMS ((size_t)BATCH * SEQ * DMODEL)  // 16777216

#define TWO_PI_OVER_DAY 7.27220521664304e-05f
#define FULLMASK 0xffffffffu

// Scratch (device globals)
__device__ float g_hfeat[HEADS * N_NODES * GDIM];  // [h][n][g] fp32
__device__ float g_es[HEADS * N_NODES];
__device__ float g_ed[HEADS * N_NODES];
__device__ float g_graph[N_NODES * DMODEL];        // [n][h*64+g], post-relu
__device__ __half g_Ah[M_TRIP * F_NODE];           // trip_batch in fp16
__device__ __half g_Bh[DMODEL * F_NODE];           // W_trip transposed [n][k] fp16

__device__ __forceinline__ void cp16(uint32_t s, const void* g) {
    asm volatile("cp.async.cg.shared.global [%0], [%1], 16;\n" :: "r"(s), "l"(g));
}

// ---------------------------------------------------------------------------
// Kernel P: fp16 prep for trip GEMM.
// ---------------------------------------------------------------------------
__global__ __launch_bounds__(256)
void k_prep(const float* __restrict__ A, const float* __restrict__ Bw) {
    const int tid = threadIdx.x;
    if (blockIdx.x < 2048) {
        const int base = (blockIdx.x * 256 + tid) * 8;
        float4 v0 = *(const float4*)(A + base);
        float4 v1 = *(const float4*)(A + base + 4);
        __half h[8];
        h[0] = __float2half(v0.x); h[1] = __float2half(v0.y);
        h[2] = __float2half(v0.z); h[3] = __float2half(v0.w);
        h[4] = __float2half(v1.x); h[5] = __float2half(v1.y);
        h[6] = __float2half(v1.z); h[7] = __float2half(v1.w);
        *(uint4*)(g_Ah + base) = *(uint4*)h;
    } else {
        const int idx = (blockIdx.x - 2048) * 256 + tid;
        const int n = idx & 511, kq = idx >> 9, k4 = kq * 4;
        __half h[4];
#pragma unroll
        for (int j = 0; j < 4; j++)
            h[j] = __float2half(Bw[(size_t)(k4 + j) * DMODEL + n]);
        *(uint2*)(g_Bh + (size_t)n * F_NODE + k4) = *(uint2*)h;
    }
}

// ---------------------------------------------------------------------------
// Kernel A: hfeat (fp32) + fused es/ed. grid 250 x 512.
// ---------------------------------------------------------------------------
__global__ __launch_bounds__(512)
void k_hfeat(const float* __restrict__ x, const float* __restrict__ W,
             const float* __restrict__ a_src, const float* __restrict__ a_dst) {
    __shared__ float xs[8][F_NODE];
    __shared__ float s_es[16][8], s_ed[16][8];
    const int nBase = blockIdx.x * 8;
    const int tid = threadIdx.x;

    for (int i = tid; i < 8 * F_NODE; i += 512)
        xs[i >> 7][i & 127] = x[nBase * F_NODE + i];
    __syncthreads();

    const int h = tid >> 6, g = tid & 63, w = tid >> 5, lane = tid & 31;
    float acc[8];
#pragma unroll
    for (int i = 0; i < 8; i++) acc[i] = 0.f;

    const float* Wp = W + (h * F_NODE) * GDIM + g;
#pragma unroll 4
    for (int f = 0; f < F_NODE; f++) {
        float wv = Wp[f * GDIM];
#pragma unroll
        for (int nn = 0; nn < 8; nn++) acc[nn] += xs[nn][f] * wv;
    }

    const float asg = a_src[h * GDIM + g], adg = a_dst[h * GDIM + g];
#pragma unroll
    for (int nn = 0; nn < 8; nn++) {
        g_hfeat[(h * N_NODES + nBase + nn) * GDIM + g] = acc[nn];
        float es = acc[nn] * asg, ed = acc[nn] * adg;
#pragma unroll
        for (int o = 16; o > 0; o >>= 1) {
            es += __shfl_xor_sync(FULLMASK, es, o);
            ed += __shfl_xor_sync(FULLMASK, ed, o);
        }
        if (lane == 0) { s_es[w][nn] = es; s_ed[w][nn] = ed; }
    }
    __syncthreads();
    if (tid < 64) {
        int hh = tid >> 3, nn = tid & 7;
        g_es[hh * N_NODES + nBase + nn] = s_es[hh * 2][nn] + s_es[hh * 2 + 1][nn];
        g_ed[hh * N_NODES + nBase + nn] = s_ed[hh * 2][nn] + s_ed[hh * 2 + 1][nn];
    }
}

// ---------------------------------------------------------------------------
// Kernel B: sparse masked softmax attention. Phase 3: zero-padded 64-tiles,
// fully unrolled, 4-wide load batches for MLP (padded entries have weight 0).
// grid 2000 x 512.
// ---------------------------------------------------------------------------
__global__ __launch_bounds__(512)
void k_attn(const float* __restrict__ adj) {
    __shared__ int s_list[N_NODES + 64];   // padded to 64-boundary with zeros
    __shared__ int s_off[17];
    __shared__ float s_m[HEADS], s_inv[HEADS];
    __shared__ float s_w[HEADS][64];
    __shared__ float4 s_red[4][128];

    const int i = blockIdx.x;
    const int tid = threadIdx.x, w = tid >> 5, lane = tid & 31;
    const float* row = adj + (size_t)i * N_NODES;
    const int base = w * 125;

    // Phase 1: compaction (16 warps x 125, ballots in registers)
    unsigned ball[4];
    int cl = 0;
#pragma unroll
    for (int t = 0; t < 4; t++) {
        int o = t * 32 + lane;
        bool v = (o < 125) && (row[base + o] > 0.f);
        ball[t] = __ballot_sync(FULLMASK, v);
        cl += __popc(ball[t]);
    }
    if (lane == 0) s_off[w + 1] = cl;
    if (tid == 0) s_off[0] = 0;
    __syncthreads();
    if (tid == 0) {
        int a = 0;
#pragma unroll
        for (int t = 1; t <= 16; t++) { a += s_off[t]; s_off[t] = a; }
    }
    __syncthreads();
    {
        int pos = s_off[w];
#pragma unroll
        for (int t = 0; t < 4; t++) {
            unsigned m = ball[t];
            if ((m >> lane) & 1u)
                s_list[pos + __popc(m & ((1u << lane) - 1u))] = base + t * 32 + lane;
            pos += __popc(m);
        }
    }
    __syncthreads();
    const int cnt = s_off[16];
    // Zero-pad s_list up to the next 64 boundary (weights there are 0).
    if (tid < 64) s_list[cnt + tid] = 0;
    __syncthreads();

    // Phase 2: per-head max & sum (warp w == head w)
    if (w < HEADS) {
        const float es_i = g_es[w * N_NODES + i];
        const float* edp = g_ed + w * N_NODES;
        float mx = -1e30f;
        for (int k = lane; k < cnt; k += 32) {
            float e = es_i + edp[s_list[k]];
            e = e >= 0.f ? e : 0.2f * e;
            mx = fmaxf(mx, e);
        }
#pragma unroll
        for (int o = 16; o > 0; o >>= 1) mx = fmaxf(mx, __shfl_xor_sync(FULLMASK, mx, o));
        float sum = 0.f;
        for (int k = lane; k < cnt; k += 32) {
            float e = es_i + edp[s_list[k]];
            e = e >= 0.f ? e : 0.2f * e;
            sum += __expf(e - mx);
        }
#pragma unroll
        for (int o = 16; o > 0; o >>= 1) sum += __shfl_xor_sync(FULLMASK, sum, o);
        if (lane == 0) { s_m[w] = mx; s_inv[w] = 1.f / sum; }
    }
    __syncthreads();

    // Phase 3: 4-way kq split, full 64-tiles, batched loads (MLP=4..16).
    const int kq = tid >> 7, sub = tid & 127;
    const int h3 = sub >> 4, g4 = (sub & 15) * 4;
    const float* hfp = g_hfeat + (size_t)h3 * N_NODES * GDIM + g4;

    const float es_w = (w < HEADS) ? g_es[w * N_NODES + i] : 0.f;
    const float* edw = g_ed + (w & 7) * N_NODES;

    float4 acc = make_float4(0.f, 0.f, 0.f, 0.f);
    for (int t0 = 0; t0 < cnt; t0 += 64) {
        if (w < HEADS) {
            const float mxw = s_m[w];
#pragma unroll
            for (int kk = lane; kk < 64; kk += 32) {
                float wt = 0.f;
                int k = t0 + kk;
                if (k < cnt) {
                    int j = s_list[k];
                    float e = es_w + edw[j];
                    e = e >= 0.f ? e : 0.2f * e;
                    wt = __expf(e - mxw);
                }
                s_w[w][kk] = wt;
            }
        }
        __syncthreads();
        const int* lp = s_list + t0;
#pragma unroll
        for (int b = 0; b < 4; b++) {
            const int k0 = kq + 16 * b;
            int j0 = lp[k0], j1 = lp[k0 + 4], j2 = lp[k0 + 8], j3 = lp[k0 + 12];
            float w0 = s_w[h3][k0],     w1 = s_w[h3][k0 + 4];
            float w2 = s_w[h3][k0 + 8], w3 = s_w[h3][k0 + 12];
            float4 v0 = *(const float4*)(hfp + (size_t)j0 * GDIM);
            float4 v1 = *(const float4*)(hfp + (size_t)j1 * GDIM);
            float4 v2 = *(const float4*)(hfp + (size_t)j2 * GDIM);
            float4 v3 = *(const float4*)(hfp + (size_t)j3 * GDIM);
            acc.x += w0 * v0.x + w1 * v1.x + w2 * v2.x + w3 * v3.x;
            acc.y += w0 * v0.y + w1 * v1.y + w2 * v2.y + w3 * v3.y;
            acc.z += w0 * v0.z + w1 * v1.z + w2 * v2.z + w3 * v3.z;
            acc.w += w0 * v0.w + w1 * v1.w + w2 * v2.w + w3 * v3.w;
        }
        __syncthreads();
    }
    s_red[kq][sub] = acc;
    __syncthreads();

    if (tid < 128) {
        float4 a0 = s_red[0][tid], a1 = s_red[1][tid];
        float4 a2 = s_red[2][tid], a3 = s_red[3][tid];
        const float inv = s_inv[tid >> 4];
        float4 r;
        r.x = fmaxf((a0.x + a1.x + a2.x + a3.x) * inv, 0.f);
        r.y = fmaxf((a0.y + a1.y + a2.y + a3.y) * inv, 0.f);
        r.z = fmaxf((a0.z + a1.z + a2.z + a3.z) * inv, 0.f);
        r.w = fmaxf((a0.w + a1.w + a2.w + a3.w) * inv, 0.f);
        *(float4*)(g_graph + (size_t)i * DMODEL + tid * 4) = r;
    }
}

// ---------------------------------------------------------------------------
// Kernel C: region output. Warp owns 8 rows; Wt/bt via __ldg per row.
// ---------------------------------------------------------------------------
__global__ __launch_bounds__(256)
void k_region(const float* __restrict__ arrive, const float* __restrict__ rmask,
              const int* __restrict__ idxarr, const float* __restrict__ Wt,
              const float* __restrict__ bt, float* __restrict__ out) {
    const int warpId = threadIdx.x >> 5, lane = threadIdx.x & 31;
    const int rowBase = blockIdx.x * 64 + warpId * 8;

    float snv = 0.f, csv = 0.f;
    int idxv = 0;
    if (lane < 8) {
        int t = rowBase + lane;
        float m = rmask[t];
        float ang = arrive[t] * TWO_PI_OVER_DAY;
        snv = __sinf(ang) * m;
        csv = __cosf(ang) * m;
        idxv = idxarr[t];
    }

#pragma unroll
    for (int r = 0; r < 8; r++) {
        float sn = __shfl_sync(FULLMASK, snv, r);
        float cs = __shfl_sync(FULLMASK, csv, r);
        int idx  = __shfl_sync(FULLMASK, idxv, r);
        const float* gp = g_graph + (size_t)(idx - 1) * DMODEL;
        float* op = out + (size_t)(rowBase + r) * DMODEL;
#pragma unroll
        for (int j = 0; j < 4; j++) {
            int d = j * 128 + lane * 4;
            float4 w0 = __ldg((const float4*)(Wt + d));
            float4 w1 = __ldg((const float4*)(Wt + DMODEL + d));
            float4 bb = __ldg((const float4*)(bt + d));
            float4 gv = make_float4(0.f, 0.f, 0.f, 0.f);
            if (idx > 0) gv = *(const float4*)(gp + d);
            float4 rr;
            rr.x = gv.x + sn * w0.x + cs * w1.x + bb.x;
            rr.y = gv.y + sn * w0.y + cs * w1.y + bb.y;
            rr.z = gv.z + sn * w0.z + cs * w1.z + bb.z;
            rr.w = gv.w + sn * w0.w + cs * w1.w + bb.w;
            *(float4*)(op + d) = rr;
        }
    }
}

// ---------------------------------------------------------------------------
// Kernel D: trip GEMM fp16 (mma.m16n8k16, fp32 acc) + time epilogue.
// 4 chunks of BK=32, all prefetched up-front (4-deep cp.async).
// ---------------------------------------------------------------------------
#define ROW_H 40
#define BUF_H (128 * ROW_H)
#define TRIP_SMEM (8 * BUF_H * 2)     // 81920 B

__device__ __forceinline__ void mma_f16(float c[4], const uint32_t a[4], const uint32_t b[2]) {
    asm volatile(
        "mma.sync.aligned.m16n8k16.row.col.f32.f16.f16.f32 "
        "{%0,%1,%2,%3}, {%4,%5,%6,%7}, {%8,%9}, {%0,%1,%2,%3};"
        : "+f"(c[0]), "+f"(c[1]), "+f"(c[2]), "+f"(c[3])
        : "r"(a[0]), "r"(a[1]), "r"(a[2]), "r"(a[3]), "r"(b[0]), "r"(b[1]));
}

__global__ __launch_bounds__(256, 2)
void k_trip(const float* __restrict__ depart, const float* __restrict__ tmask,
            const float* __restrict__ Wt, const float* __restrict__ bt,
            float* __restrict__ out) {
    extern __shared__ __half smemh[];
    __shared__ float s_sn[128], s_cs[128], s_w0[128], s_w1[128], s_bb[128];

    const int tid = threadIdx.x;
    const int rowBase = blockIdx.y * 128;
    const int colBase = blockIdx.x * 128;

    const uint32_t smem_base = (uint32_t)__cvta_generic_to_shared(smemh);

    auto prefetch = [&](int chunk, int buf) {
        const uint32_t as_a = smem_base + (uint32_t)buf * BUF_H * 2;
        const uint32_t bs_a = smem_base + (uint32_t)(4 + buf) * BUF_H * 2;
        const __half* Ag = g_Ah + (size_t)rowBase * F_NODE + chunk * 32;
        const __half* Bg = g_Bh + (size_t)colBase * F_NODE + chunk * 32;
#pragma unroll
        for (int it = 0; it < 2; it++) {
            int f = tid + it * 256;
            int rw = f >> 2, seg = f & 3;
            cp16(as_a + (uint32_t)(rw * ROW_H + seg * 8) * 2, Ag + rw * F_NODE + seg * 8);
        }
#pragma unroll
        for (int it = 0; it < 2; it++) {
            int f = tid + it * 256;
            int rw = f >> 2, seg = f & 3;
            cp16(bs_a + (uint32_t)(rw * ROW_H + seg * 8) * 2, Bg + rw * F_NODE + seg * 8);
        }
        asm volatile("cp.async.commit_group;\n");
    };

    prefetch(0, 0);
    prefetch(1, 1);

    if (tid < 128) {
        int m = rowBase + tid;
        float dm = tmask[m];
        float ang = depart[m] * TWO_PI_OVER_DAY;
        s_sn[tid] = __sinf(ang) * dm;
        s_cs[tid] = __cosf(ang) * dm;
    } else {
        int c = tid - 128;
        int n = colBase + c;
        s_w0[c] = Wt[n];
        s_w1[c] = Wt[DMODEL + n];
        s_bb[c] = bt[n];
    }

    prefetch(2, 2);
    prefetch(3, 3);

    const int warpId = tid >> 5, lane = tid & 31;
    const int wm = warpId >> 2, wn = warpId & 3;
    const int wmBase = wm * 64, wnBase = wn * 32;
    const int q = lane >> 2, r = lane & 3;

    float c[4][4][4];
#pragma unroll
    for (int mi = 0; mi < 4; mi++)
#pragma unroll
        for (int ni = 0; ni < 4; ni++)
#pragma unroll
            for (int j = 0; j < 4; j++) c[mi][ni][j] = 0.f;

#pragma unroll
    for (int ch = 0; ch < 4; ch++) {
        if (ch == 0)      asm volatile("cp.async.wait_group 3;\n");
        else if (ch == 1) asm volatile("cp.async.wait_group 2;\n");
        else if (ch == 2) asm volatile("cp.async.wait_group 1;\n");
        else              asm volatile("cp.async.wait_group 0;\n");
        __syncthreads();

        const uint32_t* Aw = (const uint32_t*)(smemh + (size_t)ch * BUF_H);
        const uint32_t* Bw = (const uint32_t*)(smemh + (size_t)(4 + ch) * BUF_H);
#pragma unroll
        for (int kk2 = 0; kk2 < 16; kk2 += 8) {
            uint32_t a[4][4], b[4][2];
#pragma unroll
            for (int mi = 0; mi < 4; mi++) {
                int row = wmBase + mi * 16 + q;
                a[mi][0] = Aw[row * 20 + kk2 + r];
                a[mi][1] = Aw[(row + 8) * 20 + kk2 + r];
                a[mi][2] = Aw[row * 20 + kk2 + 4 + r];
                a[mi][3] = Aw[(row + 8) * 20 + kk2 + 4 + r];
            }
#pragma unroll
            for (int ni = 0; ni < 4; ni++) {
                int col = wnBase + ni * 8 + q;
                b[ni][0] = Bw[col * 20 + kk2 + r];
                b[ni][1] = Bw[col * 20 + kk2 + 4 + r];
            }
#pragma unroll
            for (int mi = 0; mi < 4; mi++)
#pragma unroll
                for (int ni = 0; ni < 4; ni++)
                    mma_f16(c[mi][ni], a[mi], b[ni]);
        }
    }

    __syncthreads();
    float* outT = out + REGION_ELEMS;
#pragma unroll
    for (int mi = 0; mi < 4; mi++) {
        int lr0 = wmBase + mi * 16 + q;
#pragma unroll
        for (int ni = 0; ni < 4; ni++) {
            int lc = wnBase + ni * 8 + 2 * r;
            float w0a = s_w0[lc], w0b = s_w0[lc + 1];
            float w1a = s_w1[lc], w1b = s_w1[lc + 1];
            float ba  = s_bb[lc], bb_ = s_bb[lc + 1];
#pragma unroll
            for (int half = 0; half < 2; half++) {
                int lr = lr0 + half * 8;
                float sn = s_sn[lr], cs = s_cs[lr];
                float v0 = fmaxf(c[mi][ni][half * 2 + 0], 0.f) + sn * w0a + cs * w1a + ba;
                float v1 = fmaxf(c[mi][ni][half * 2 + 1], 0.f) + sn * w0b + cs * w1b + bb_;
                *(float2*)(outT + (size_t)(rowBase + lr) * DMODEL + colBase + lc) =
                    make_float2(v0, v1);
            }
        }
    }
}

// ---------------------------------------------------------------------------
extern "C" void kernel_launch(void* const* d_in, const int* in_sizes, int n_in,
                              void* d_out, int out_size) {
    const float* region_batch = (const float*)d_in[0];
    const float* trip_batch   = (const float*)d_in[1];
    const float* trip_mask    = (const float*)d_in[2];
    const float* region_mask  = (const float*)d_in[3];
    const float* graph_mask   = (const float*)d_in[4];
    const float* arrive       = (const float*)d_in[5];
    const float* depart       = (const float*)d_in[6];
    const int*   index_array  = (const int*)d_in[7];
    const float* W_trip       = (const float*)d_in[8];
    const float* W_gat        = (const float*)d_in[9];
    const float* a_src        = (const float*)d_in[10];
    const float* a_dst        = (const float*)d_in[11];
    const float* W_time       = (const float*)d_in[12];
    const float* b_time       = (const float*)d_in[13];
    float* out = (float*)d_out;

    cudaFuncSetAttribute(k_trip, cudaFuncAttributeMaxDynamicSharedMemorySize, TRIP_SMEM);

    // Order: prep, hfeat, trip, attn (profiled 4th), region.
    k_prep<<<2112, 256>>>(trip_batch, W_trip);
    k_hfeat<<<250, 512>>>(region_batch, W_gat, a_src, a_dst);
    dim3 gridE(DMODEL / 128, M_TRIP / 128);
    k_trip<<<gridE, 256, TRIP_SMEM>>>(depart, trip_mask, W_time, b_time, out);
    k_attn<<<N_NODES, 512>>>(graph_mask);
    k_region<<<M_TRIP / 64, 256>>>(arrive, region_mask, index_array,
                                   W_time, b_time, out);
}

// round 13
// speedup vs baseline: 1.0957x; 1.0957x over previous
#include <cuda_runtime.h>
#include <cuda_fp16.h>
#include <math.h>
#include <stdint.h>

// Problem constants
#define N_NODES 2000
#define F_NODE  128
#define HEADS   8
#define GDIM    64
#define DMODEL  512
#define BATCH   64
#define SEQ     512
#define M_TRIP  (BATCH * SEQ)
#define REGION_ELEMS ((size_t)BATCH * SEQ * DMODEL)  // 16777216

#define TWO_PI_OVER_DAY 7.27220521664304e-05f
#define FULLMASK 0xffffffffu

// Scratch (device globals)
__device__ float g_hfeat[HEADS * N_NODES * GDIM];  // [h][n][g] fp32
__device__ float g_es[HEADS * N_NODES];
__device__ float g_ed[HEADS * N_NODES];
__device__ float g_graph[N_NODES * DMODEL];        // [n][h*64+g], post-relu
__device__ __half g_Ah[M_TRIP * F_NODE];           // trip_batch in fp16
__device__ __half g_Bh[DMODEL * F_NODE];           // W_trip transposed [n][k] fp16

__device__ __forceinline__ void cp16(uint32_t s, const void* g) {
    asm volatile("cp.async.cg.shared.global [%0], [%1], 16;\n" :: "r"(s), "l"(g));
}

// ---------------------------------------------------------------------------
// Kernel A: hfeat (fp32) + fused es/ed, PLUS fp16 prep in extra blocks.
// grid 1290 x 512: [0,250) hfeat, [250,1274) A-convert, [1274,1290) B-convert.
// ---------------------------------------------------------------------------
__global__ __launch_bounds__(512)
void k_hfeat(const float* __restrict__ x, const float* __restrict__ W,
             const float* __restrict__ a_src, const float* __restrict__ a_dst,
             const float* __restrict__ Atrip, const float* __restrict__ Btrip) {
    const int tid = threadIdx.x;

    if (blockIdx.x >= 250) {
        const int b = blockIdx.x - 250;
        if (b < 1024) {
            // A conversion: 1024 blocks x 512 threads x 8 elems = 4,194,304
            const int base = (b * 512 + tid) * 8;
            float4 v0 = *(const float4*)(Atrip + base);
            float4 v1 = *(const float4*)(Atrip + base + 4);
            __half h[8];
            h[0] = __float2half(v0.x); h[1] = __float2half(v0.y);
            h[2] = __float2half(v0.z); h[3] = __float2half(v0.w);
            h[4] = __float2half(v1.x); h[5] = __float2half(v1.y);
            h[6] = __float2half(v1.z); h[7] = __float2half(v1.w);
            *(uint4*)(g_Ah + base) = *(uint4*)h;
        } else {
            // B transpose+convert: 16 blocks x 512 threads x 8 elems = 65,536
            const int idx = (b - 1024) * 512 + tid;     // [0, 8192)
            const int n = idx & 511, k0 = (idx >> 9) * 8;
            __half h[8];
#pragma unroll
            for (int j = 0; j < 8; j++)
                h[j] = __float2half(Btrip[(size_t)(k0 + j) * DMODEL + n]);
            *(uint4*)(g_Bh + (size_t)n * F_NODE + k0) = *(uint4*)h;
        }
        return;
    }

    __shared__ float xs[8][F_NODE];
    __shared__ float s_es[16][8], s_ed[16][8];
    const int nBase = blockIdx.x * 8;

    for (int i = tid; i < 8 * F_NODE; i += 512)
        xs[i >> 7][i & 127] = x[nBase * F_NODE + i];
    __syncthreads();

    const int h = tid >> 6, g = tid & 63, w = tid >> 5, lane = tid & 31;
    float acc[8];
#pragma unroll
    for (int i = 0; i < 8; i++) acc[i] = 0.f;

    const float* Wp = W + (h * F_NODE) * GDIM + g;
#pragma unroll 4
    for (int f = 0; f < F_NODE; f++) {
        float wv = Wp[f * GDIM];
#pragma unroll
        for (int nn = 0; nn < 8; nn++) acc[nn] += xs[nn][f] * wv;
    }

    const float asg = a_src[h * GDIM + g], adg = a_dst[h * GDIM + g];
#pragma unroll
    for (int nn = 0; nn < 8; nn++) {
        g_hfeat[(h * N_NODES + nBase + nn) * GDIM + g] = acc[nn];
        float es = acc[nn] * asg, ed = acc[nn] * adg;
#pragma unroll
        for (int o = 16; o > 0; o >>= 1) {
            es += __shfl_xor_sync(FULLMASK, es, o);
            ed += __shfl_xor_sync(FULLMASK, ed, o);
        }
        if (lane == 0) { s_es[w][nn] = es; s_ed[w][nn] = ed; }
    }
    __syncthreads();
    if (tid < 64) {
        int hh = tid >> 3, nn = tid & 7;
        g_es[hh * N_NODES + nBase + nn] = s_es[hh * 2][nn] + s_es[hh * 2 + 1][nn];
        g_ed[hh * N_NODES + nBase + nn] = s_ed[hh * 2][nn] + s_ed[hh * 2 + 1][nn];
    }
}

// ---------------------------------------------------------------------------
// Kernel B: sparse masked softmax attention (R10 version — measured 30.1us).
// grid 2000 x 512.
// ---------------------------------------------------------------------------
__global__ __launch_bounds__(512)
void k_attn(const float* __restrict__ adj) {
    __shared__ int s_list[N_NODES];
    __shared__ int s_off[17];
    __shared__ float s_m[HEADS], s_inv[HEADS];
    __shared__ float s_w[HEADS][64];
    __shared__ float4 s_red[4][128];

    const int i = blockIdx.x;
    const int tid = threadIdx.x, w = tid >> 5, lane = tid & 31;
    const float* row = adj + (size_t)i * N_NODES;
    const int base = w * 125;

    unsigned ball[4];
    int cl = 0;
#pragma unroll
    for (int t = 0; t < 4; t++) {
        int o = t * 32 + lane;
        bool v = (o < 125) && (row[base + o] > 0.f);
        ball[t] = __ballot_sync(FULLMASK, v);
        cl += __popc(ball[t]);
    }
    if (lane == 0) s_off[w + 1] = cl;
    if (tid == 0) s_off[0] = 0;
    __syncthreads();
    if (tid == 0) {
        int a = 0;
#pragma unroll
        for (int t = 1; t <= 16; t++) { a += s_off[t]; s_off[t] = a; }
    }
    __syncthreads();
    {
        int pos = s_off[w];
#pragma unroll
        for (int t = 0; t < 4; t++) {
            unsigned m = ball[t];
            if ((m >> lane) & 1u)
                s_list[pos + __popc(m & ((1u << lane) - 1u))] = base + t * 32 + lane;
            pos += __popc(m);
        }
    }
    __syncthreads();
    const int cnt = s_off[16];

    if (w < HEADS) {
        const float es_i = g_es[w * N_NODES + i];
        const float* edp = g_ed + w * N_NODES;
        float mx = -1e30f;
        for (int k = lane; k < cnt; k += 32) {
            float e = es_i + edp[s_list[k]];
            e = e >= 0.f ? e : 0.2f * e;
            mx = fmaxf(mx, e);
        }
#pragma unroll
        for (int o = 16; o > 0; o >>= 1) mx = fmaxf(mx, __shfl_xor_sync(FULLMASK, mx, o));
        float sum = 0.f;
        for (int k = lane; k < cnt; k += 32) {
            float e = es_i + edp[s_list[k]];
            e = e >= 0.f ? e : 0.2f * e;
            sum += __expf(e - mx);
        }
#pragma unroll
        for (int o = 16; o > 0; o >>= 1) sum += __shfl_xor_sync(FULLMASK, sum, o);
        if (lane == 0) { s_m[w] = mx; s_inv[w] = 1.f / sum; }
    }
    __syncthreads();

    const int kq = tid >> 7, sub = tid & 127;
    const int h3 = sub >> 4, g4 = (sub & 15) * 4;
    const float* hfp = g_hfeat + (size_t)h3 * N_NODES * GDIM + g4;

    const float es_w = (w < HEADS) ? g_es[w * N_NODES + i] : 0.f;
    const float* edw = g_ed + (w & 7) * N_NODES;

    float4 acc = make_float4(0.f, 0.f, 0.f, 0.f);
    for (int t0 = 0; t0 < cnt; t0 += 64) {
        if (w < HEADS) {
            const float mxw = s_m[w];
#pragma unroll
            for (int kk = lane; kk < 64; kk += 32) {
                float wt = 0.f;
                int k = t0 + kk;
                if (k < cnt) {
                    int j = s_list[k];
                    float e = es_w + edw[j];
                    e = e >= 0.f ? e : 0.2f * e;
                    wt = __expf(e - mxw);
                }
                s_w[w][kk] = wt;
            }
        }
        __syncthreads();
        const int tlen = min(64, cnt - t0);
        for (int k = kq; k < tlen; k += 4) {
            int j = s_list[t0 + k];
            float wv = s_w[h3][k];
            float4 gv = *(const float4*)(hfp + (size_t)j * GDIM);
            acc.x += wv * gv.x;
            acc.y += wv * gv.y;
            acc.z += wv * gv.z;
            acc.w += wv * gv.w;
        }
        __syncthreads();
    }
    s_red[kq][sub] = acc;
    __syncthreads();

    if (tid < 128) {
        float4 a0 = s_red[0][tid], a1 = s_red[1][tid];
        float4 a2 = s_red[2][tid], a3 = s_red[3][tid];
        const float inv = s_inv[tid >> 4];
        float4 r;
        r.x = fmaxf((a0.x + a1.x + a2.x + a3.x) * inv, 0.f);
        r.y = fmaxf((a0.y + a1.y + a2.y + a3.y) * inv, 0.f);
        r.z = fmaxf((a0.z + a1.z + a2.z + a3.z) * inv, 0.f);
        r.w = fmaxf((a0.w + a1.w + a2.w + a3.w) * inv, 0.f);
        *(float4*)(g_graph + (size_t)i * DMODEL + tid * 4) = r;
    }
}

// ---------------------------------------------------------------------------
// Kernel C: region output. Warp owns 8 rows; Wt/bt via __ldg; streaming stores.
// ---------------------------------------------------------------------------
__global__ __launch_bounds__(256)
void k_region(const float* __restrict__ arrive, const float* __restrict__ rmask,
              const int* __restrict__ idxarr, const float* __restrict__ Wt,
              const float* __restrict__ bt, float* __restrict__ out) {
    const int warpId = threadIdx.x >> 5, lane = threadIdx.x & 31;
    const int rowBase = blockIdx.x * 64 + warpId * 8;

    float snv = 0.f, csv = 0.f;
    int idxv = 0;
    if (lane < 8) {
        int t = rowBase + lane;
        float m = rmask[t];
        float ang = arrive[t] * TWO_PI_OVER_DAY;
        snv = __sinf(ang) * m;
        csv = __cosf(ang) * m;
        idxv = idxarr[t];
    }

#pragma unroll
    for (int r = 0; r < 8; r++) {
        float sn = __shfl_sync(FULLMASK, snv, r);
        float cs = __shfl_sync(FULLMASK, csv, r);
        int idx  = __shfl_sync(FULLMASK, idxv, r);
        const float* gp = g_graph + (size_t)(idx - 1) * DMODEL;
        float* op = out + (size_t)(rowBase + r) * DMODEL;
#pragma unroll
        for (int j = 0; j < 4; j++) {
            int d = j * 128 + lane * 4;
            float4 w0 = __ldg((const float4*)(Wt + d));
            float4 w1 = __ldg((const float4*)(Wt + DMODEL + d));
            float4 bb = __ldg((const float4*)(bt + d));
            float4 gv = make_float4(0.f, 0.f, 0.f, 0.f);
            if (idx > 0) gv = *(const float4*)(gp + d);
            float4 rr;
            rr.x = gv.x + sn * w0.x + cs * w1.x + bb.x;
            rr.y = gv.y + sn * w0.y + cs * w1.y + bb.y;
            rr.z = gv.z + sn * w0.z + cs * w1.z + bb.z;
            rr.w = gv.w + sn * w0.w + cs * w1.w + bb.w;
            __stcs((float4*)(op + d), rr);   // streaming: written once, never read
        }
    }
}

// ---------------------------------------------------------------------------
// Kernel D: trip GEMM fp16 (mma.m16n8k16, fp32 acc) + time epilogue.
// 4 chunks of BK=32, all prefetched up-front (4-deep cp.async).
// ---------------------------------------------------------------------------
#define ROW_H 40
#define BUF_H (128 * ROW_H)
#define TRIP_SMEM (8 * BUF_H * 2)     // 81920 B

__device__ __forceinline__ void mma_f16(float c[4], const uint32_t a[4], const uint32_t b[2]) {
    asm volatile(
        "mma.sync.aligned.m16n8k16.row.col.f32.f16.f16.f32 "
        "{%0,%1,%2,%3}, {%4,%5,%6,%7}, {%8,%9}, {%0,%1,%2,%3};"
        : "+f"(c[0]), "+f"(c[1]), "+f"(c[2]), "+f"(c[3])
        : "r"(a[0]), "r"(a[1]), "r"(a[2]), "r"(a[3]), "r"(b[0]), "r"(b[1]));
}

__global__ __launch_bounds__(256, 2)
void k_trip(const float* __restrict__ depart, const float* __restrict__ tmask,
            const float* __restrict__ Wt, const float* __restrict__ bt,
            float* __restrict__ out) {
    extern __shared__ __half smemh[];
    __shared__ float s_sn[128], s_cs[128], s_w0[128], s_w1[128], s_bb[128];

    const int tid = threadIdx.x;
    const int rowBase = blockIdx.y * 128;
    const int colBase = blockIdx.x * 128;

    const uint32_t smem_base = (uint32_t)__cvta_generic_to_shared(smemh);

    auto prefetch = [&](int chunk, int buf) {
        const uint32_t as_a = smem_base + (uint32_t)buf * BUF_H * 2;
        const uint32_t bs_a = smem_base + (uint32_t)(4 + buf) * BUF_H * 2;
        const __half* Ag = g_Ah + (size_t)rowBase * F_NODE + chunk * 32;
        const __half* Bg = g_Bh + (size_t)colBase * F_NODE + chunk * 32;
#pragma unroll
        for (int it = 0; it < 2; it++) {
            int f = tid + it * 256;
            int rw = f >> 2, seg = f & 3;
            cp16(as_a + (uint32_t)(rw * ROW_H + seg * 8) * 2, Ag + rw * F_NODE + seg * 8);
        }
#pragma unroll
        for (int it = 0; it < 2; it++) {
            int f = tid + it * 256;
            int rw = f >> 2, seg = f & 3;
            cp16(bs_a + (uint32_t)(rw * ROW_H + seg * 8) * 2, Bg + rw * F_NODE + seg * 8);
        }
        asm volatile("cp.async.commit_group;\n");
    };

    prefetch(0, 0);
    prefetch(1, 1);

    if (tid < 128) {
        int m = rowBase + tid;
        float dm = tmask[m];
        float ang = depart[m] * TWO_PI_OVER_DAY;
        s_sn[tid] = __sinf(ang) * dm;
        s_cs[tid] = __cosf(ang) * dm;
    } else {
        int c = tid - 128;
        int n = colBase + c;
        s_w0[c] = Wt[n];
        s_w1[c] = Wt[DMODEL + n];
        s_bb[c] = bt[n];
    }

    prefetch(2, 2);
    prefetch(3, 3);

    const int warpId = tid >> 5, lane = tid & 31;
    const int wm = warpId >> 2, wn = warpId & 3;
    const int wmBase = wm * 64, wnBase = wn * 32;
    const int q = lane >> 2, r = lane & 3;

    float c[4][4][4];
#pragma unroll
    for (int mi = 0; mi < 4; mi++)
#pragma unroll
        for (int ni = 0; ni < 4; ni++)
#pragma unroll
            for (int j = 0; j < 4; j++) c[mi][ni][j] = 0.f;

#pragma unroll
    for (int ch = 0; ch < 4; ch++) {
        if (ch == 0)      asm volatile("cp.async.wait_group 3;\n");
        else if (ch == 1) asm volatile("cp.async.wait_group 2;\n");
        else if (ch == 2) asm volatile("cp.async.wait_group 1;\n");
        else              asm volatile("cp.async.wait_group 0;\n");
        __syncthreads();

        const uint32_t* Aw = (const uint32_t*)(smemh + (size_t)ch * BUF_H);
        const uint32_t* Bw = (const uint32_t*)(smemh + (size_t)(4 + ch) * BUF_H);
#pragma unroll
        for (int kk2 = 0; kk2 < 16; kk2 += 8) {
            uint32_t a[4][4], b[4][2];
#pragma unroll
            for (int mi = 0; mi < 4; mi++) {
                int row = wmBase + mi * 16 + q;
                a[mi][0] = Aw[row * 20 + kk2 + r];
                a[mi][1] = Aw[(row + 8) * 20 + kk2 + r];
                a[mi][2] = Aw[row * 20 + kk2 + 4 + r];
                a[mi][3] = Aw[(row + 8) * 20 + kk2 + 4 + r];
            }
#pragma unroll
            for (int ni = 0; ni < 4; ni++) {
                int col = wnBase + ni * 8 + q;
                b[ni][0] = Bw[col * 20 + kk2 + r];
                b[ni][1] = Bw[col * 20 + kk2 + 4 + r];
            }
#pragma unroll
            for (int mi = 0; mi < 4; mi++)
#pragma unroll
                for (int ni = 0; ni < 4; ni++)
                    mma_f16(c[mi][ni], a[mi], b[ni]);
        }
    }

    __syncthreads();
    float* outT = out + REGION_ELEMS;
#pragma unroll
    for (int mi = 0; mi < 4; mi++) {
        int lr0 = wmBase + mi * 16 + q;
#pragma unroll
        for (int ni = 0; ni < 4; ni++) {
            int lc = wnBase + ni * 8 + 2 * r;
            float w0a = s_w0[lc], w0b = s_w0[lc + 1];
            float w1a = s_w1[lc], w1b = s_w1[lc + 1];
            float ba  = s_bb[lc], bb_ = s_bb[lc + 1];
#pragma unroll
            for (int half = 0; half < 2; half++) {
                int lr = lr0 + half * 8;
                float sn = s_sn[lr], cs = s_cs[lr];
                float v0 = fmaxf(c[mi][ni][half * 2 + 0], 0.f) + sn * w0a + cs * w1a + ba;
                float v1 = fmaxf(c[mi][ni][half * 2 + 1], 0.f) + sn * w0b + cs * w1b + bb_;
                __stcs((float2*)(outT + (size_t)(rowBase + lr) * DMODEL + colBase + lc),
                       make_float2(v0, v1));
            }
        }
    }
}

// ---------------------------------------------------------------------------
extern "C" void kernel_launch(void* const* d_in, const int* in_sizes, int n_in,
                              void* d_out, int out_size) {
    const float* region_batch = (const float*)d_in[0];
    const float* trip_batch   = (const float*)d_in[1];
    const float* trip_mask    = (const float*)d_in[2];
    const float* region_mask  = (const float*)d_in[3];
    const float* graph_mask   = (const float*)d_in[4];
    const float* arrive       = (const float*)d_in[5];
    const float* depart       = (const float*)d_in[6];
    const int*   index_array  = (const int*)d_in[7];
    const float* W_trip       = (const float*)d_in[8];
    const float* W_gat        = (const float*)d_in[9];
    const float* a_src        = (const float*)d_in[10];
    const float* a_dst        = (const float*)d_in[11];
    const float* W_time       = (const float*)d_in[12];
    const float* b_time       = (const float*)d_in[13];
    float* out = (float*)d_out;

    cudaFuncSetAttribute(k_trip, cudaFuncAttributeMaxDynamicSharedMemorySize, TRIP_SMEM);

    // 4 launches: hfeat(+prep), trip, attn, region (profiled 4th).
    k_hfeat<<<1290, 512>>>(region_batch, W_gat, a_src, a_dst, trip_batch, W_trip);
    dim3 gridE(DMODEL / 128, M_TRIP / 128);
    k_trip<<<gridE, 256, TRIP_SMEM>>>(depart, trip_mask, W_time, b_time, out);
    k_attn<<<N_NODES, 512>>>(graph_mask);
    k_region<<<M_TRIP / 64, 256>>>(arrive, region_mask, index_array,
                                   W_time, b_time, out);
}